// round 1
// baseline (speedup 1.0000x reference)
#include <cuda_runtime.h>
#include <cstdint>

// Problem constants
#define NV   512          // num variables
#define NH   64           // hidden dim
#define NB   4096         // batch

// Tiling
#define BM   128          // batch rows per block
#define BK   32           // K (=V) slice per smem stage
// BN = NH = 64 (full hidden dim per block)

#define XS_STRIDE 36      // 32 + 4 pad: bank(r,k) = (4r + k) % 32 -> bijective over (g,t)
#define WS_STRIDE 68      // 64 + 4 pad: bank(k,n) = (4k + n) % 32 -> bijective over (t,g)

__device__ __forceinline__ float to_tf32_rna(float x) {
    uint32_t u;
    asm("cvt.rna.tf32.f32 %0, %1;" : "=r"(u) : "f"(x));
    return __uint_as_float(u);
}

__device__ __forceinline__ void mma_tf32(float c[4], const uint32_t a[4], const uint32_t b[2]) {
    asm volatile(
        "mma.sync.aligned.m16n8k8.row.col.f32.tf32.tf32.f32 "
        "{%0,%1,%2,%3}, {%4,%5,%6,%7}, {%8,%9}, {%0,%1,%2,%3};"
        : "+f"(c[0]), "+f"(c[1]), "+f"(c[2]), "+f"(c[3])
        : "r"(a[0]), "r"(a[1]), "r"(a[2]), "r"(a[3]),
          "r"(b[0]), "r"(b[1]));
}

// One block: network i = blockIdx.y, batch tile blockIdx.x (BM rows).
// Computes h = relu( (X .* adj[:,i]) @ W1[i] + b1[i] ), recon = h @ W2[i] + b2[i].
__global__ __launch_bounds__(256) void dag_mma_kernel(
    const float* __restrict__ X,        // [NB, NV]
    const float* __restrict__ logits,   // [NV, NV]
    const float* __restrict__ W1,       // [NV, NV, NH]
    const float* __restrict__ b1,       // [NV, NH]
    const float* __restrict__ W2,       // [NV, NH]
    const float* __restrict__ b2,       // [NV]
    float* __restrict__ out)            // [NB, NV] (recon part)
{
    __shared__ float Xs[BM][XS_STRIDE];   // masked + tf32-rounded X tile
    __shared__ float Ws[BK][WS_STRIDE];   // tf32-rounded W1[i] tile
    __shared__ float adjm[NV];            // adjacency mask column for network i
    __shared__ float red[4][BM];          // cross-warp reduction buffer

    const int i     = blockIdx.y;
    const int bbase = blockIdx.x * BM;
    const int tid   = threadIdx.x;
    const int warp  = tid >> 5;
    const int lane  = tid & 31;
    const int wm    = warp >> 2;      // 0..1 : 64-row half
    const int wn    = warp & 3;       // 0..3 : 16-col slice
    const int g     = lane >> 2;      // 0..7
    const int t     = lane & 3;       // 0..3

    // Build adjacency mask column: adj[v, i] = (logits[v,i] > 0) && (v != i)
    for (int v = tid; v < NV; v += 256) {
        adjm[v] = (logits[v * NV + i] > 0.0f && v != i) ? 1.0f : 0.0f;
    }
    __syncthreads();

    float acc[4][2][4];                // [m-tile][n-tile][c-frag]
    #pragma unroll
    for (int mt = 0; mt < 4; mt++)
        #pragma unroll
        for (int nt = 0; nt < 2; nt++)
            #pragma unroll
            for (int q = 0; q < 4; q++) acc[mt][nt][q] = 0.0f;

    for (int kb = 0; kb < NV; kb += BK) {
        // --- Load X tile [BM x BK], apply mask along K, round to tf32 ---
        #pragma unroll
        for (int l = 0; l < 4; l++) {
            int e   = tid + l * 256;            // 0..1023 float4 slots
            int row = e >> 3;                   // 0..127
            int c4  = (e & 7) * 4;              // 0..28
            float4 xv = *reinterpret_cast<const float4*>(
                &X[(size_t)(bbase + row) * NV + kb + c4]);
            float m0 = adjm[kb + c4 + 0];
            float m1 = adjm[kb + c4 + 1];
            float m2 = adjm[kb + c4 + 2];
            float m3 = adjm[kb + c4 + 3];
            float4 sv;
            sv.x = to_tf32_rna(xv.x * m0);
            sv.y = to_tf32_rna(xv.y * m1);
            sv.z = to_tf32_rna(xv.z * m2);
            sv.w = to_tf32_rna(xv.w * m3);
            *reinterpret_cast<float4*>(&Xs[row][c4]) = sv;
        }
        // --- Load W1[i] tile [BK x NH], round to tf32 ---
        #pragma unroll
        for (int l = 0; l < 2; l++) {
            int e  = tid + l * 256;             // 0..511 float4 slots
            int kr = e >> 4;                    // 0..31
            int c4 = (e & 15) * 4;              // 0..60
            float4 wv = *reinterpret_cast<const float4*>(
                &W1[((size_t)i * NV + kb + kr) * NH + c4]);
            float4 sv;
            sv.x = to_tf32_rna(wv.x);
            sv.y = to_tf32_rna(wv.y);
            sv.z = to_tf32_rna(wv.z);
            sv.w = to_tf32_rna(wv.w);
            *reinterpret_cast<float4*>(&Ws[kr][c4]) = sv;
        }
        __syncthreads();

        // --- Compute: 4 k8-steps x (4 m-tiles x 2 n-tiles) mma ---
        #pragma unroll
        for (int ks = 0; ks < 4; ks++) {
            const int k0 = ks * 8;
            uint32_t afr[4][4];
            #pragma unroll
            for (int mt = 0; mt < 4; mt++) {
                int r = wm * 64 + mt * 16 + g;
                afr[mt][0] = __float_as_uint(Xs[r    ][k0 + t    ]);
                afr[mt][1] = __float_as_uint(Xs[r + 8][k0 + t    ]);
                afr[mt][2] = __float_as_uint(Xs[r    ][k0 + t + 4]);
                afr[mt][3] = __float_as_uint(Xs[r + 8][k0 + t + 4]);
            }
            uint32_t bfr[2][2];
            #pragma unroll
            for (int nt = 0; nt < 2; nt++) {
                int n0 = wn * 16 + nt * 8 + g;
                bfr[nt][0] = __float_as_uint(Ws[k0 + t    ][n0]);
                bfr[nt][1] = __float_as_uint(Ws[k0 + t + 4][n0]);
            }
            #pragma unroll
            for (int mt = 0; mt < 4; mt++)
                #pragma unroll
                for (int nt = 0; nt < 2; nt++)
                    mma_tf32(acc[mt][nt], afr[mt], bfr[nt]);
        }
        __syncthreads();
    }

    // --- Epilogue: recon_row = sum_h relu(acc + b1[i,h]) * W2[i,h]  (+ b2[i]) ---
    // c-frag mapping (m16n8): c0=(g,2t), c1=(g,2t+1), c2=(g+8,2t), c3=(g+8,2t+1)
    const float* b1i = &b1[(size_t)i * NH];
    const float* W2i = &W2[(size_t)i * NH];

    #pragma unroll
    for (int mt = 0; mt < 4; mt++) {
        #pragma unroll
        for (int half = 0; half < 2; half++) {   // row = base + g  or  base + 8 + g
            float sum = 0.0f;
            #pragma unroll
            for (int nt = 0; nt < 2; nt++) {
                int col = wn * 16 + nt * 8 + 2 * t;
                float c0 = acc[mt][nt][half * 2 + 0];
                float c1 = acc[mt][nt][half * 2 + 1];
                float h0 = fmaxf(c0 + b1i[col],     0.0f);
                float h1 = fmaxf(c1 + b1i[col + 1], 0.0f);
                sum += h0 * W2i[col] + h1 * W2i[col + 1];
            }
            // reduce across t (4 lanes: xor 1, 2)
            sum += __shfl_xor_sync(0xFFFFFFFFu, sum, 1);
            sum += __shfl_xor_sync(0xFFFFFFFFu, sum, 2);
            if (t == 0) {
                int row = wm * 64 + mt * 16 + half * 8 + g;
                red[wn][row] = sum;
            }
        }
    }
    __syncthreads();

    if (tid < BM) {
        float r = red[0][tid] + red[1][tid] + red[2][tid] + red[3][tid] + b2[i];
        out[(size_t)(bbase + tid) * NV + i] = r;
    }
}

// Writes adj [NV, NV] into out + NB*NV
__global__ void adj_kernel(const float* __restrict__ logits, float* __restrict__ out)
{
    int idx = blockIdx.x * blockDim.x + threadIdx.x;
    if (idx < NV * NV) {
        int v = idx / NV;
        int u = idx % NV;
        out[(size_t)NB * NV + idx] =
            (logits[idx] > 0.0f && v != u) ? 1.0f : 0.0f;
    }
}

extern "C" void kernel_launch(void* const* d_in, const int* in_sizes, int n_in,
                              void* d_out, int out_size)
{
    const float* X      = (const float*)d_in[0];   // [4096, 512]
    const float* logits = (const float*)d_in[1];   // [512, 512]
    const float* W1     = (const float*)d_in[2];   // [512, 512, 64]
    const float* b1     = (const float*)d_in[3];   // [512, 64]
    const float* W2     = (const float*)d_in[4];   // [512, 64]
    const float* b2     = (const float*)d_in[5];   // [512]
    float* out          = (float*)d_out;           // [4096*512 + 512*512]

    dim3 grid(NB / BM, NV);     // (32, 512)
    dag_mma_kernel<<<grid, 256>>>(X, logits, W1, b1, W2, b2, out);

    adj_kernel<<<(NV * NV + 255) / 256, 256>>>(logits, out);
}

// round 7
// speedup vs baseline: 1.4879x; 1.4879x over previous
#include <cuda_runtime.h>
#include <cuda_fp16.h>
#include <cstdint>

#define NV 512
#define NH 64
#define NB 4096

#define BM 256            // batch rows per block
#define GN 2              // networks per block -> BN = 128
#define BK 32             // K slice per stage
#define NSTAGES 16        // NV / BK
#define PIPE 3            // cp.async pipeline depth

// smem per stage: A = 256 rows * 80B (40 fp16, 32 data + 8 pad), B = 128 * 80B
#define A_ROW_B   80
#define A_BYTES   (BM * A_ROW_B)        // 20480
#define B_BYTES   (128 * A_ROW_B)      // 10240
#define STAGE_B   (A_BYTES + B_BYTES)  // 30720
#define SM_PARAMS (PIPE * STAGE_B)     // 92160
#define SMEM_MAIN (SM_PARAMS + 2048)   // params: b1s 512, w2s 512, b2s 8

// scratch (static device memory — allowed)
__device__ __half g_W1T[(size_t)NV * NH * NV];   // [i][h][v]  masked fp16, 32 MB
__device__ __half g_X16[(size_t)NB * NV];        // [b][v] fp16, 4 MB

__device__ __forceinline__ uint32_t smem_u32(const void* p) {
    uint32_t a;
    asm("{ .reg .u64 t; cvta.to.shared.u64 t, %1; cvt.u32.u64 %0, t; }" : "=r"(a) : "l"(p));
    return a;
}

__device__ __forceinline__ void cp16(uint32_t dst, const void* src) {
    asm volatile("cp.async.ca.shared.global [%0], [%1], 16;" :: "r"(dst), "l"(src));
}
__device__ __forceinline__ void cp_commit() {
    asm volatile("cp.async.commit_group;");
}

__device__ __forceinline__ void mma_f16(float c[4], const uint32_t a[4], const uint32_t b[2]) {
    asm volatile(
        "mma.sync.aligned.m16n8k16.row.col.f32.f16.f16.f32 "
        "{%0,%1,%2,%3}, {%4,%5,%6,%7}, {%8,%9}, {%0,%1,%2,%3};"
        : "+f"(c[0]), "+f"(c[1]), "+f"(c[2]), "+f"(c[3])
        : "r"(a[0]), "r"(a[1]), "r"(a[2]), "r"(a[3]), "r"(b[0]), "r"(b[1]));
}

// ---------------- pre-pass: X -> fp16 ----------------
__global__ __launch_bounds__(256) void conv_x_kernel(const float* __restrict__ X) {
    int idx = blockIdx.x * 256 + threadIdx.x;       // 524288 float4 tasks
    float4 v = reinterpret_cast<const float4*>(X)[idx];
    __half2* o = reinterpret_cast<__half2*>(g_X16) + idx * 2;
    o[0] = __floats2half2_rn(v.x, v.y);
    o[1] = __floats2half2_rn(v.z, v.w);
}

// ---------------- pre-pass: W1_eff = mask(W1), transpose -> [i][h][v], fp16 ----------------
// one block per network i
#define CW_SMEM (NV * 66 * 2 + NV * 4)   // tile[512][66] half + adj[512] float = 69632
__global__ __launch_bounds__(256) void conv_w1t_kernel(const float* __restrict__ W1,
                                                       const float* __restrict__ logits) {
    extern __shared__ char smem[];
    __half* tile = reinterpret_cast<__half*>(smem);              // [v][66]
    float* adjs  = reinterpret_cast<float*>(smem + NV * 66 * 2); // [v]
    const int i   = blockIdx.x;
    const int tid = threadIdx.x;

    #pragma unroll
    for (int l = 0; l < 2; l++) {
        int v = tid + l * 256;
        adjs[v] = (logits[(size_t)v * NV + i] > 0.0f && v != i) ? 1.0f : 0.0f;
    }
    __syncthreads();

    const float2* w = reinterpret_cast<const float2*>(W1 + (size_t)i * NV * NH);
    #pragma unroll
    for (int l = 0; l < 64; l++) {
        int e = tid + l * 256;          // 16384 float2 tasks over [v][h]
        int v = e >> 5, h2i = e & 31;
        float2 x = w[e];
        float m = adjs[v];
        tile[v * 66 + 2 * h2i]     = __float2half_rn(x.x * m);
        tile[v * 66 + 2 * h2i + 1] = __float2half_rn(x.y * m);
    }
    __syncthreads();

    #pragma unroll
    for (int l = 0; l < 64; l++) {
        int h  = l;
        int v2 = 2 * tid;
        __half2 o;
        o.x = tile[v2 * 66 + h];
        o.y = tile[(v2 + 1) * 66 + h];
        reinterpret_cast<__half2*>(g_W1T + ((size_t)i * NH + h) * NV)[tid] = o;
    }
}

// ---------------- main GEMM + fused epilogue ----------------
__global__ __launch_bounds__(256, 1)
void dag_f16_kernel(const float* __restrict__ b1,
                    const float* __restrict__ W2,
                    const float* __restrict__ b2,
                    float* __restrict__ out)
{
    extern __shared__ char smem[];
    const uint32_t sb = smem_u32(smem);
    const int tid  = threadIdx.x;
    const int warp = tid >> 5;
    const int lane = tid & 31;
    const int g    = lane >> 2;          // 0..7
    const int t    = lane & 3;           // 0..3
    const int wn   = warp & 1;           // net within block
    const int wm   = warp >> 1;          // 0..3 : 64-row slice

    const int i0    = blockIdx.y * GN;
    const int bbase = blockIdx.x * BM;

    // params -> smem
    float* b1s = reinterpret_cast<float*>(smem + SM_PARAMS);          // [2][64]
    float* w2s = reinterpret_cast<float*>(smem + SM_PARAMS + 512);    // [2][64]
    float* b2s = reinterpret_cast<float*>(smem + SM_PARAMS + 1024);   // [2]
    if (tid < 128) {
        int net = tid >> 6, h = tid & 63;
        b1s[tid] = b1[(size_t)(i0 + net) * NH + h];
        w2s[tid] = W2[(size_t)(i0 + net) * NH + h];
        if (tid < GN) b2s[tid] = b2[i0 + tid];
    }

    float acc[4][8][4];
    #pragma unroll
    for (int mt = 0; mt < 4; mt++)
        #pragma unroll
        for (int nt = 0; nt < 8; nt++)
            #pragma unroll
            for (int q = 0; q < 4; q++) acc[mt][nt][q] = 0.0f;

    // per-thread load descriptors
    // A: 1024 16B chunks, 4 per thread; B: 512 chunks, 2 per thread
    auto load_stage = [&](int s) {
        const int kb  = s * BK;
        const int buf = s % PIPE;
        const uint32_t aB = sb + buf * STAGE_B;
        const uint32_t bB = aB + A_BYTES;
        #pragma unroll
        for (int l = 0; l < 4; l++) {
            int c = tid + l * 256;
            int row = c >> 2, q = c & 3;
            cp16(aB + row * A_ROW_B + q * 16,
                 g_X16 + (size_t)(bbase + row) * NV + kb + q * 8);
        }
        #pragma unroll
        for (int l = 0; l < 2; l++) {
            int c = tid + l * 256;
            int n = c >> 2, q = c & 3;
            int net = n >> 6, h = n & 63;
            cp16(bB + n * A_ROW_B + q * 16,
                 g_W1T + ((size_t)(i0 + net) * NH + h) * NV + kb + q * 8);
        }
        cp_commit();
    };

    load_stage(0);
    load_stage(1);

    for (int s = 0; s < NSTAGES; s++) {
        if (s < NSTAGES - 2) {
            asm volatile("cp.async.wait_group 1;" ::: "memory");
        } else {
            asm volatile("cp.async.wait_group 0;" ::: "memory");
        }
        __syncthreads();
        if (s + 2 < NSTAGES) load_stage(s + 2);

        const int buf = s % PIPE;
        const char* aB = smem + buf * STAGE_B;
        const char* bB = aB + A_BYTES;

        #pragma unroll
        for (int kk = 0; kk < 2; kk++) {
            uint32_t afr[4][4];
            #pragma unroll
            for (int mt = 0; mt < 4; mt++) {
                int r = wm * 64 + mt * 16 + g;
                const char* p = aB + (r * 20 + kk * 8 + t) * 4;
                afr[mt][0] = *reinterpret_cast<const uint32_t*>(p);
                afr[mt][1] = *reinterpret_cast<const uint32_t*>(p + 640);     // row +8
                afr[mt][2] = *reinterpret_cast<const uint32_t*>(p + 16);      // k +8
                afr[mt][3] = *reinterpret_cast<const uint32_t*>(p + 656);
            }
            uint32_t bfr[8][2];
            #pragma unroll
            for (int nt = 0; nt < 8; nt++) {
                int n = wn * 64 + nt * 8 + g;
                const char* p = bB + (n * 20 + kk * 8 + t) * 4;
                bfr[nt][0] = *reinterpret_cast<const uint32_t*>(p);
                bfr[nt][1] = *reinterpret_cast<const uint32_t*>(p + 16);
            }
            #pragma unroll
            for (int mt = 0; mt < 4; mt++)
                #pragma unroll
                for (int nt = 0; nt < 8; nt++)
                    mma_f16(acc[mt][nt], afr[mt], bfr[nt]);
        }
        __syncthreads();
    }

    // epilogue: recon[row][i0+wn] = sum_h relu(acc + b1) * w2 + b2
    const int i = i0 + wn;
    #pragma unroll
    for (int mt = 0; mt < 4; mt++) {
        #pragma unroll
        for (int half = 0; half < 2; half++) {
            float sum = 0.0f;
            #pragma unroll
            for (int nt = 0; nt < 8; nt++) {
                int col = wn * 64 + nt * 8 + 2 * t;
                float c0 = acc[mt][nt][half * 2 + 0];
                float c1 = acc[mt][nt][half * 2 + 1];
                sum += fmaxf(c0 + b1s[col],     0.0f) * w2s[col];
                sum += fmaxf(c1 + b1s[col + 1], 0.0f) * w2s[col + 1];
            }
            sum += __shfl_xor_sync(0xFFFFFFFFu, sum, 1);
            sum += __shfl_xor_sync(0xFFFFFFFFu, sum, 2);
            if (t == 0) {
                int row = bbase + wm * 64 + mt * 16 + half * 8 + g;
                out[(size_t)row * NV + i] = sum + b2s[wn];
            }
        }
    }
}

// adjacency block of output
__global__ void adj_kernel(const float* __restrict__ logits, float* __restrict__ out) {
    int idx = blockIdx.x * blockDim.x + threadIdx.x;
    if (idx < NV * NV) {
        int v = idx / NV, u = idx % NV;
        out[(size_t)NB * NV + idx] = (logits[idx] > 0.0f && v != u) ? 1.0f : 0.0f;
    }
}

extern "C" void kernel_launch(void* const* d_in, const int* in_sizes, int n_in,
                              void* d_out, int out_size)
{
    const float* X      = (const float*)d_in[0];
    const float* logits = (const float*)d_in[1];
    const float* W1     = (const float*)d_in[2];
    const float* b1     = (const float*)d_in[3];
    const float* W2     = (const float*)d_in[4];
    const float* b2     = (const float*)d_in[5];
    float* out          = (float*)d_out;

    static bool attr_done = false;
    if (!attr_done) {
        cudaFuncSetAttribute(conv_w1t_kernel, cudaFuncAttributeMaxDynamicSharedMemorySize, CW_SMEM);
        cudaFuncSetAttribute(dag_f16_kernel,  cudaFuncAttributeMaxDynamicSharedMemorySize, SMEM_MAIN);
        attr_done = true;
    }

    conv_x_kernel<<<NB * NV / 4 / 256, 256>>>(X);
    conv_w1t_kernel<<<NV, 256, CW_SMEM>>>(W1, logits);

    dim3 grid(NB / BM, NV / GN);   // (16, 256)
    dag_f16_kernel<<<grid, 256, SMEM_MAIN>>>(b1, W2, b2, out);

    adj_kernel<<<(NV * NV + 255) / 256, 256>>>(logits, out);
}

// round 8
// speedup vs baseline: 2.2234x; 1.4943x over previous
#include <cuda_runtime.h>
#include <cuda_fp16.h>
#include <cstdint>

#define NV 512
#define NH 64
#define NB 4096

#define BM 128            // batch rows per block
#define GN 2              // networks per block -> BN = 128
#define BK 32             // K slice per stage
#define NSTAGES 16        // NV / BK
#define PIPE 4            // cp.async pipeline depth

// smem per stage: A = 128 rows * 80B (40 fp16: 32 data + 8 pad), B = 128 * 80B
#define A_ROW_B   80
#define A_BYTES   (BM * A_ROW_B)        // 10240
#define B_BYTES   (128 * A_ROW_B)       // 10240
#define STAGE_B   (A_BYTES + B_BYTES)   // 20480
#define SM_PARAMS (PIPE * STAGE_B)      // 81920
#define SMEM_MAIN (SM_PARAMS + 2048)    // + b1s/w2s/b2s

// scratch (static device memory — allowed)
__device__ __half g_W1T[(size_t)NV * NH * NV];   // [i][h][v]  masked fp16, 32 MB
__device__ __half g_X16[(size_t)NB * NV];        // [b][v] fp16, 4 MB

__device__ __forceinline__ uint32_t smem_u32(const void* p) {
    uint32_t a;
    asm("{ .reg .u64 t; cvta.to.shared.u64 t, %1; cvt.u32.u64 %0, t; }" : "=r"(a) : "l"(p));
    return a;
}

__device__ __forceinline__ void cp16(uint32_t dst, const void* src) {
    asm volatile("cp.async.ca.shared.global [%0], [%1], 16;" :: "r"(dst), "l"(src));
}
__device__ __forceinline__ void cp_commit() {
    asm volatile("cp.async.commit_group;");
}

__device__ __forceinline__ void mma_f16(float c[4], const uint32_t a[4], const uint32_t b[2]) {
    asm volatile(
        "mma.sync.aligned.m16n8k16.row.col.f32.f16.f16.f32 "
        "{%0,%1,%2,%3}, {%4,%5,%6,%7}, {%8,%9}, {%0,%1,%2,%3};"
        : "+f"(c[0]), "+f"(c[1]), "+f"(c[2]), "+f"(c[3])
        : "r"(a[0]), "r"(a[1]), "r"(a[2]), "r"(a[3]), "r"(b[0]), "r"(b[1]));
}

// ---------------- pre-pass: X -> fp16 ----------------
__global__ __launch_bounds__(256) void conv_x_kernel(const float* __restrict__ X) {
    int idx = blockIdx.x * 256 + threadIdx.x;       // 524288 float4 tasks
    float4 v = reinterpret_cast<const float4*>(X)[idx];
    __half2* o = reinterpret_cast<__half2*>(g_X16) + idx * 2;
    o[0] = __floats2half2_rn(v.x, v.y);
    o[1] = __floats2half2_rn(v.z, v.w);
}

// ---------------- pre-pass: W1_eff = mask(W1), transpose -> [i][h][v], fp16 ----------------
#define CW_SMEM (NV * 66 * 2 + NV * 4)   // tile[512][66] half + adj[512] float
__global__ __launch_bounds__(256) void conv_w1t_kernel(const float* __restrict__ W1,
                                                       const float* __restrict__ logits) {
    extern __shared__ char smem[];
    __half* tile = reinterpret_cast<__half*>(smem);              // [v][66]
    float* adjs  = reinterpret_cast<float*>(smem + NV * 66 * 2); // [v]
    const int i   = blockIdx.x;
    const int tid = threadIdx.x;

    #pragma unroll
    for (int l = 0; l < 2; l++) {
        int v = tid + l * 256;
        adjs[v] = (logits[(size_t)v * NV + i] > 0.0f && v != i) ? 1.0f : 0.0f;
    }
    __syncthreads();

    const float2* w = reinterpret_cast<const float2*>(W1 + (size_t)i * NV * NH);
    #pragma unroll
    for (int l = 0; l < 64; l++) {
        int e = tid + l * 256;          // 16384 float2 tasks over [v][h]
        int v = e >> 5, h2i = e & 31;
        float2 x = w[e];
        float m = adjs[v];
        tile[v * 66 + 2 * h2i]     = __float2half_rn(x.x * m);
        tile[v * 66 + 2 * h2i + 1] = __float2half_rn(x.y * m);
    }
    __syncthreads();

    #pragma unroll
    for (int l = 0; l < 64; l++) {
        int h  = l;
        int v2 = 2 * tid;
        __half2 o;
        o.x = tile[v2 * 66 + h];
        o.y = tile[(v2 + 1) * 66 + h];
        reinterpret_cast<__half2*>(g_W1T + ((size_t)i * NH + h) * NV)[tid] = o;
    }
}

// ---------------- main GEMM + fused epilogue ----------------
__global__ __launch_bounds__(256, 2)
void dag_f16_kernel(const float* __restrict__ b1,
                    const float* __restrict__ W2,
                    const float* __restrict__ b2,
                    float* __restrict__ out)
{
    extern __shared__ char smem[];
    const uint32_t sb = smem_u32(smem);
    const int tid  = threadIdx.x;
    const int warp = tid >> 5;
    const int lane = tid & 31;
    const int g    = lane >> 2;          // 0..7
    const int t    = lane & 3;           // 0..3
    const int wn   = warp & 1;           // net within block (64-col half)
    const int wm   = warp >> 1;          // 0..3 : 32-row slice

    const int i0    = blockIdx.y * GN;
    const int bbase = blockIdx.x * BM;

    // params -> smem
    float* b1s = reinterpret_cast<float*>(smem + SM_PARAMS);          // [2][64]
    float* w2s = reinterpret_cast<float*>(smem + SM_PARAMS + 512);    // [2][64]
    float* b2s = reinterpret_cast<float*>(smem + SM_PARAMS + 1024);   // [2]
    if (tid < 128) {
        int net = tid >> 6, h = tid & 63;
        b1s[tid] = b1[(size_t)(i0 + net) * NH + h];
        w2s[tid] = W2[(size_t)(i0 + net) * NH + h];
        if (tid < GN) b2s[tid] = b2[i0 + tid];
    }

    float acc[2][8][4];
    #pragma unroll
    for (int mt = 0; mt < 2; mt++)
        #pragma unroll
        for (int nt = 0; nt < 8; nt++)
            #pragma unroll
            for (int q = 0; q < 4; q++) acc[mt][nt][q] = 0.0f;

    // A: 512 16B chunks (2/thread); B: 512 chunks (2/thread)
    auto load_stage = [&](int s) {
        const int kb  = s * BK;
        const int buf = s % PIPE;
        const uint32_t aB = sb + buf * STAGE_B;
        const uint32_t bB = aB + A_BYTES;
        #pragma unroll
        for (int l = 0; l < 2; l++) {
            int c = tid + l * 256;
            int row = c >> 2, q = c & 3;
            cp16(aB + row * A_ROW_B + q * 16,
                 g_X16 + (size_t)(bbase + row) * NV + kb + q * 8);
        }
        #pragma unroll
        for (int l = 0; l < 2; l++) {
            int c = tid + l * 256;
            int n = c >> 2, q = c & 3;
            int net = n >> 6, h = n & 63;
            cp16(bB + n * A_ROW_B + q * 16,
                 g_W1T + ((size_t)(i0 + net) * NH + h) * NV + kb + q * 8);
        }
        cp_commit();
    };

    load_stage(0);
    load_stage(1);
    load_stage(2);

    for (int s = 0; s < NSTAGES; s++) {
        // 3 groups pending at this point (s, s+1, s+2 or empties) -> wait until s done
        asm volatile("cp.async.wait_group 2;" ::: "memory");
        __syncthreads();
        if (s + 3 < NSTAGES) load_stage(s + 3);
        else cp_commit();   // empty group keeps the pending count uniform

        const int buf = s % PIPE;
        const char* aB = smem + buf * STAGE_B;
        const char* bB = aB + A_BYTES;

        #pragma unroll
        for (int kk = 0; kk < 2; kk++) {
            uint32_t afr[2][4];
            #pragma unroll
            for (int mt = 0; mt < 2; mt++) {
                int r = wm * 32 + mt * 16 + g;
                const char* p = aB + (r * 20 + kk * 8 + t) * 4;
                afr[mt][0] = *reinterpret_cast<const uint32_t*>(p);
                afr[mt][1] = *reinterpret_cast<const uint32_t*>(p + 640);   // row +8
                afr[mt][2] = *reinterpret_cast<const uint32_t*>(p + 16);    // k +8
                afr[mt][3] = *reinterpret_cast<const uint32_t*>(p + 656);
            }
            uint32_t bfr[8][2];
            #pragma unroll
            for (int nt = 0; nt < 8; nt++) {
                int n = wn * 64 + nt * 8 + g;
                const char* p = bB + (n * 20 + kk * 8 + t) * 4;
                bfr[nt][0] = *reinterpret_cast<const uint32_t*>(p);
                bfr[nt][1] = *reinterpret_cast<const uint32_t*>(p + 16);
            }
            #pragma unroll
            for (int mt = 0; mt < 2; mt++)
                #pragma unroll
                for (int nt = 0; nt < 8; nt++)
                    mma_f16(acc[mt][nt], afr[mt], bfr[nt]);
        }
        // no trailing sync: the next iteration's top barrier protects buffer reuse
        // (loads issued in iter s target buf (s+3)%4, last read in iter s-1)
    }

    // epilogue: recon[row][i0+wn] = sum_h relu(acc + b1) * w2 + b2
    const int i = i0 + wn;
    #pragma unroll
    for (int mt = 0; mt < 2; mt++) {
        #pragma unroll
        for (int half = 0; half < 2; half++) {
            float sum = 0.0f;
            #pragma unroll
            for (int nt = 0; nt < 8; nt++) {
                int col = wn * 64 + nt * 8 + 2 * t;
                float c0 = acc[mt][nt][half * 2 + 0];
                float c1 = acc[mt][nt][half * 2 + 1];
                sum += fmaxf(c0 + b1s[col],     0.0f) * w2s[col];
                sum += fmaxf(c1 + b1s[col + 1], 0.0f) * w2s[col + 1];
            }
            sum += __shfl_xor_sync(0xFFFFFFFFu, sum, 1);
            sum += __shfl_xor_sync(0xFFFFFFFFu, sum, 2);
            if (t == 0) {
                int row = bbase + wm * 32 + mt * 16 + half * 8 + g;
                out[(size_t)row * NV + i] = sum + b2s[wn];
            }
        }
    }
}

// adjacency block of output
__global__ void adj_kernel(const float* __restrict__ logits, float* __restrict__ out) {
    int idx = blockIdx.x * blockDim.x + threadIdx.x;
    if (idx < NV * NV) {
        int v = idx / NV, u = idx % NV;
        out[(size_t)NB * NV + idx] = (logits[idx] > 0.0f && v != u) ? 1.0f : 0.0f;
    }
}

extern "C" void kernel_launch(void* const* d_in, const int* in_sizes, int n_in,
                              void* d_out, int out_size)
{
    const float* X      = (const float*)d_in[0];
    const float* logits = (const float*)d_in[1];
    const float* W1     = (const float*)d_in[2];
    const float* b1     = (const float*)d_in[3];
    const float* W2     = (const float*)d_in[4];
    const float* b2     = (const float*)d_in[5];
    float* out          = (float*)d_out;

    static bool attr_done = false;
    if (!attr_done) {
        cudaFuncSetAttribute(conv_w1t_kernel, cudaFuncAttributeMaxDynamicSharedMemorySize, CW_SMEM);
        cudaFuncSetAttribute(dag_f16_kernel,  cudaFuncAttributeMaxDynamicSharedMemorySize, SMEM_MAIN);
        attr_done = true;
    }

    conv_x_kernel<<<NB * NV / 4 / 256, 256>>>(X);
    conv_w1t_kernel<<<NV, 256, CW_SMEM>>>(W1, logits);

    dim3 grid(NB / BM, NV / GN);   // (32, 256)
    dag_f16_kernel<<<grid, 256, SMEM_MAIN>>>(b1, W2, b2, out);

    adj_kernel<<<(NV * NV + 255) / 256, 256>>>(logits, out);
}

// round 9
// speedup vs baseline: 3.4968x; 1.5727x over previous
#include <cuda_runtime.h>
#include <cuda_fp16.h>
#include <cstdint>

#define NV 512
#define NH 64
#define NB 4096

#define BM 128            // batch rows per block
#define GN 2              // networks per block -> BN = 128
#define BK 32             // K slice per stage
#define PIPE 4            // cp.async pipeline depth

// ---- main-kernel smem layout ----
// A: per net, BK k-rows x 128 halfs (256B) + 16B pad -> pitch 272
#define A_PITCH   272
#define A_NET_B   (BK * A_PITCH)          // 8704
#define A_BYTES   (GN * A_NET_B)          // 17408
#define B_ROW_B   80                      // 32 halfs + 8 pad
#define B_BYTES   (128 * B_ROW_B)         // 10240
#define STAGE_B   (A_BYTES + B_BYTES)     // 27648
#define SM_PARAMS (PIPE * STAGE_B)        // 110592
#define SM_IDX    (SM_PARAMS + 1152)      // u16[2][512] = 2048 B
#define SMEM_MAIN (SM_IDX + 2048)         // 113792 -> 2 CTA/SM = 227584 <= 233472

// ---- static scratch (allowed) ----
__device__ __half   g_WC[(size_t)NV * NH * NV];  // [i][h][k'] compacted, zero-padded; 32 MB
__device__ __half   g_XT[(size_t)NV * NB];       // [v][b] fp16 transpose of X; 4 MB
__device__ uint16_t g_idx[NV * NV];              // [i][k'] active-parent list, 0-padded
__device__ int      g_cnt[NV];                   // active-parent count per net

__device__ __forceinline__ uint32_t smem_u32(const void* p) {
    uint32_t a;
    asm("{ .reg .u64 t; cvta.to.shared.u64 t, %1; cvt.u32.u64 %0, t; }" : "=r"(a) : "l"(p));
    return a;
}
__device__ __forceinline__ void cp16(uint32_t dst, const void* src) {
    asm volatile("cp.async.ca.shared.global [%0], [%1], 16;" :: "r"(dst), "l"(src));
}
__device__ __forceinline__ void cp_commit() {
    asm volatile("cp.async.commit_group;");
}
__device__ __forceinline__ void mma_f16(float c[4], const uint32_t a[4], const uint32_t b[2]) {
    asm volatile(
        "mma.sync.aligned.m16n8k16.row.col.f32.f16.f16.f32 "
        "{%0,%1,%2,%3}, {%4,%5,%6,%7}, {%8,%9}, {%0,%1,%2,%3};"
        : "+f"(c[0]), "+f"(c[1]), "+f"(c[2]), "+f"(c[3])
        : "r"(a[0]), "r"(a[1]), "r"(a[2]), "r"(a[3]), "r"(b[0]), "r"(b[1]));
}
#define LDMX4T(d, a) \
    asm volatile("ldmatrix.sync.aligned.m8n8.x4.trans.shared.b16 {%0,%1,%2,%3}, [%4];" \
        : "=r"((d)[0]), "=r"((d)[1]), "=r"((d)[2]), "=r"((d)[3]) : "r"(a))

// ---------------- pre-pass 1: X -> XT[v][b] fp16 ----------------
__global__ __launch_bounds__(256) void xt_kernel(const float* __restrict__ X) {
    __shared__ float tile[64][65];
    const int tx = threadIdx.x & 63, ty = threadIdx.x >> 6;   // 64 x 4
    const int b0 = blockIdx.x * 64, v0 = blockIdx.y * 64;
    #pragma unroll
    for (int j = 0; j < 16; j++) {
        int row = ty + j * 4;
        tile[row][tx] = X[(size_t)(b0 + row) * NV + v0 + tx];
    }
    __syncthreads();
    #pragma unroll
    for (int j = 0; j < 16; j++) {
        int v = ty + j * 4;
        g_XT[(size_t)(v0 + v) * NB + b0 + tx] = __float2half_rn(tile[tx][v]);
    }
}

// ---------------- pre-pass 2: per-net compaction ----------------
// builds g_idx[i][*], g_cnt[i], and g_WC[i][h][k'] = W1[i][idx[k']][h] (0 beyond cnt)
#define CWS_MASK (NV * 66 * 2)            // tile[512][66] half = 67584
#define CWS_SIDX (CWS_MASK + 64)          // u16[512]
#define CWS_CNT  (CWS_SIDX + 1024)
#define CW_SMEM  (CWS_CNT + 16)           // ~68.7 KB
__global__ __launch_bounds__(256) void compact_kernel(const float* __restrict__ W1,
                                                      const float* __restrict__ logits) {
    extern __shared__ char cs[];
    __half*   tile  = reinterpret_cast<__half*>(cs);
    uint32_t* masks = reinterpret_cast<uint32_t*>(cs + CWS_MASK);
    uint16_t* sidx  = reinterpret_cast<uint16_t*>(cs + CWS_SIDX);
    int*      scnt  = reinterpret_cast<int*>(cs + CWS_CNT);
    const int i = blockIdx.x, tid = threadIdx.x;
    const int warp = tid >> 5, lane = tid & 31;

    bool bits[2];
    #pragma unroll
    for (int r = 0; r < 2; r++) {
        int v = tid + r * 256;
        bits[r] = (logits[(size_t)v * NV + i] > 0.0f) && (v != i);
        uint32_t m = __ballot_sync(0xFFFFFFFFu, bits[r]);
        if (lane == 0) masks[warp + r * 8] = m;
    }
    __syncthreads();
    #pragma unroll
    for (int r = 0; r < 2; r++) {
        int v = tid + r * 256;
        int wi = warp + r * 8;
        int base = 0;
        for (int j = 0; j < wi; j++) base += __popc(masks[j]);
        int pos = base + __popc(masks[wi] & ((1u << lane) - 1u));
        if (bits[r]) sidx[pos] = (uint16_t)v;
    }
    if (tid == 0) {
        int c = 0;
        for (int j = 0; j < 16; j++) c += __popc(masks[j]);
        scnt[0] = c;
        g_cnt[i] = c;
    }
    __syncthreads();
    const int cnt = scnt[0];
    for (int k = tid; k < NV; k += 256)
        g_idx[i * NV + k] = (k < cnt) ? sidx[k] : (uint16_t)0;

    // load W1[i] into smem tile[v][h] (fp16)
    const float2* w = reinterpret_cast<const float2*>(W1 + (size_t)i * NV * NH);
    #pragma unroll
    for (int l = 0; l < 64; l++) {
        int e = tid + l * 256;            // 16384 float2 over [v][h]
        int v = e >> 5, h2i = e & 31;
        float2 x = w[e];
        tile[v * 66 + 2 * h2i]     = __float2half_rn(x.x);
        tile[v * 66 + 2 * h2i + 1] = __float2half_rn(x.y);
    }
    __syncthreads();

    // compacted write: WC[i][h][k'] (zero-padded to 512)
    #pragma unroll
    for (int l = 0; l < 64; l++) {
        int f = tid + l * 256;            // 16384 over h(64) x kp(256)
        int h = f >> 8, kp = f & 255;
        int k0 = 2 * kp, k1 = k0 + 1;
        __half2 o;
        o.x = (k0 < cnt) ? tile[(int)sidx[k0] * 66 + h] : __half(0.0f);
        o.y = (k1 < cnt) ? tile[(int)sidx[k1] * 66 + h] : __half(0.0f);
        reinterpret_cast<__half2*>(g_WC + (((size_t)i * NH + h) << 9))[kp] = o;
    }
}

// ---------------- main GEMM + fused epilogue ----------------
__global__ __launch_bounds__(256, 2)
void dag_f16_kernel(const float* __restrict__ b1,
                    const float* __restrict__ W2,
                    const float* __restrict__ b2,
                    float* __restrict__ out)
{
    extern __shared__ char smem[];
    const uint32_t sb = smem_u32(smem);
    const int tid  = threadIdx.x;
    const int warp = tid >> 5;
    const int lane = tid & 31;
    const int g    = lane >> 2;
    const int t    = lane & 3;
    const int wn   = warp & 1;           // net within block
    const int wm   = warp >> 1;          // 0..3 : 32-row slice

    const int i0    = blockIdx.y * GN;
    const int bbase = blockIdx.x * BM;

    float* b1s = reinterpret_cast<float*>(smem + SM_PARAMS);
    float* w2s = reinterpret_cast<float*>(smem + SM_PARAMS + 512);
    float* b2s = reinterpret_cast<float*>(smem + SM_PARAMS + 1024);
    uint16_t* idxs = reinterpret_cast<uint16_t*>(smem + SM_IDX);   // [2][512]
    if (tid < 128) {
        int net = tid >> 6, h = tid & 63;
        b1s[tid] = b1[(size_t)(i0 + net) * NH + h];
        w2s[tid] = W2[(size_t)(i0 + net) * NH + h];
        if (tid < GN) b2s[tid] = b2[i0 + tid];
    }
    {   // load both nets' index lists (1024 u16 = 512 u32)
        const uint32_t* src = reinterpret_cast<const uint32_t*>(g_idx + (size_t)i0 * NV);
        uint32_t* dst = reinterpret_cast<uint32_t*>(idxs);
        dst[tid] = src[tid];
        dst[tid + 256] = src[tid + 256];
    }
    int c0 = g_cnt[i0], c1 = g_cnt[i0 + 1];
    const int ns = ((c0 > c1 ? c0 : c1) + 31) >> 5;
    __syncthreads();

    float acc[2][8][4];
    #pragma unroll
    for (int mt = 0; mt < 2; mt++)
        #pragma unroll
        for (int nt = 0; nt < 8; nt++)
            #pragma unroll
            for (int q = 0; q < 4; q++) acc[mt][nt][q] = 0.0f;

    auto load_stage = [&](int s) {
        const int buf = s & 3;
        const uint32_t aB = sb + buf * STAGE_B;
        const uint32_t bB = aB + A_BYTES;
        #pragma unroll
        for (int l = 0; l < 4; l++) {         // A: 1024 chunks, gathered rows of XT
            int c = tid + l * 256;
            int net = c >> 9, krow = (c >> 4) & 31, mc = c & 15;
            uint32_t xrow = idxs[net * NV + s * BK + krow];
            cp16(aB + net * A_NET_B + krow * A_PITCH + mc * 16,
                 g_XT + (size_t)xrow * NB + bbase + mc * 8);
        }
        #pragma unroll
        for (int l = 0; l < 2; l++) {         // B: 512 chunks from compact WC
            int c = tid + l * 256;
            int n = c >> 2, q = c & 3;
            int net = n >> 6, h = n & 63;
            cp16(bB + n * B_ROW_B + q * 16,
                 g_WC + (((size_t)(i0 + net) * NH + h) << 9) + s * BK + q * 8);
        }
        cp_commit();
    };

    #pragma unroll
    for (int sp = 0; sp < 3; sp++) {
        if (sp < ns) load_stage(sp); else cp_commit();
    }

    // per-lane ldmatrix address components (constant across stages)
    const int lr   = lane & 7;
    const int sel  = lane >> 3;
    const int kofs = (sel & 2) ? 8 : 0;
    const int mofs = (sel & 1) ? 8 : 0;
    const uint32_t a_lane_off =
        (uint32_t)((kofs + lr) * A_PITCH + (wm * 32 + mofs) * 2) + wn * A_NET_B;

    for (int s = 0; s < ns; s++) {
        asm volatile("cp.async.wait_group 2;" ::: "memory");
        __syncthreads();
        if (s + 3 < ns) load_stage(s + 3); else cp_commit();

        const int buf = s & 3;
        const uint32_t aB = sb + buf * STAGE_B + a_lane_off;
        const char* bBc = smem + buf * STAGE_B + A_BYTES;

        #pragma unroll
        for (int kk = 0; kk < 2; kk++) {
            uint32_t afr[2][4];
            #pragma unroll
            for (int mt = 0; mt < 2; mt++) {
                uint32_t addr = aB + kk * (16 * A_PITCH) + mt * 32;
                LDMX4T(afr[mt], addr);
            }
            uint32_t bfr[8][2];
            #pragma unroll
            for (int nt = 0; nt < 8; nt++) {
                int n = wn * 64 + nt * 8 + g;
                const char* p = bBc + (n * 20 + kk * 8 + t) * 4;
                bfr[nt][0] = *reinterpret_cast<const uint32_t*>(p);
                bfr[nt][1] = *reinterpret_cast<const uint32_t*>(p + 16);
            }
            #pragma unroll
            for (int mt = 0; mt < 2; mt++)
                #pragma unroll
                for (int nt = 0; nt < 8; nt++)
                    mma_f16(acc[mt][nt], afr[mt], bfr[nt]);
        }
    }

    // epilogue: recon[row][i0+wn] = sum_h relu(acc + b1) * w2 + b2
    const int i = i0 + wn;
    #pragma unroll
    for (int mt = 0; mt < 2; mt++) {
        #pragma unroll
        for (int half = 0; half < 2; half++) {
            float sum = 0.0f;
            #pragma unroll
            for (int nt = 0; nt < 8; nt++) {
                int col = wn * 64 + nt * 8 + 2 * t;
                float v0 = acc[mt][nt][half * 2 + 0];
                float v1 = acc[mt][nt][half * 2 + 1];
                sum += fmaxf(v0 + b1s[col],     0.0f) * w2s[col];
                sum += fmaxf(v1 + b1s[col + 1], 0.0f) * w2s[col + 1];
            }
            sum += __shfl_xor_sync(0xFFFFFFFFu, sum, 1);
            sum += __shfl_xor_sync(0xFFFFFFFFu, sum, 2);
            if (t == 0) {
                int row = bbase + wm * 32 + mt * 16 + half * 8 + g;
                out[(size_t)row * NV + i] = sum + b2s[wn];
            }
        }
    }
}

// adjacency block of output
__global__ void adj_kernel(const float* __restrict__ logits, float* __restrict__ out) {
    int idx = blockIdx.x * blockDim.x + threadIdx.x;
    if (idx < NV * NV) {
        int v = idx / NV, u = idx % NV;
        out[(size_t)NB * NV + idx] = (logits[idx] > 0.0f && v != u) ? 1.0f : 0.0f;
    }
}

extern "C" void kernel_launch(void* const* d_in, const int* in_sizes, int n_in,
                              void* d_out, int out_size)
{
    const float* X      = (const float*)d_in[0];
    const float* logits = (const float*)d_in[1];
    const float* W1     = (const float*)d_in[2];
    const float* b1     = (const float*)d_in[3];
    const float* W2     = (const float*)d_in[4];
    const float* b2     = (const float*)d_in[5];
    float* out          = (float*)d_out;

    static bool attr_done = false;
    if (!attr_done) {
        cudaFuncSetAttribute(compact_kernel, cudaFuncAttributeMaxDynamicSharedMemorySize, CW_SMEM);
        cudaFuncSetAttribute(dag_f16_kernel, cudaFuncAttributeMaxDynamicSharedMemorySize, SMEM_MAIN);
        attr_done = true;
    }

    dim3 xtg(NB / 64, NV / 64);           // (64, 8)
    xt_kernel<<<xtg, 256>>>(X);
    compact_kernel<<<NV, 256, CW_SMEM>>>(W1, logits);

    dim3 grid(NB / BM, NV / GN);          // (32, 256)
    dag_f16_kernel<<<grid, 256, SMEM_MAIN>>>(b1, W2, b2, out);

    adj_kernel<<<(NV * NV + 255) / 256, 256>>>(logits, out);
}